// round 11
// baseline (speedup 1.0000x reference)
#include <cuda_runtime.h>
#include <cuda_bf16.h>

// BSplineNN: out[b,c] = sum_n coef[b,n,c] * B_{n,3}(x_b)
// B=4096, n=64, C=256, K=3, T=68.
// Two kernels + L2 PREFETCH:
//  K1 (spans): 1 warp/row computes span j; lane 0 immediately issues
//     cp.async.bulk.prefetch.L2 of the row's 4 KB coef window (fire-and-
//     forget, async engine -> not bounded by SM demand-miss tracking).
//     Then closed-form weights -> scratch (L2-hot).
//  K2 (gather): 1 warp/row; (w4, base) L2 hits, then 8x LDG.128 that now
//     hit L2 (or merge with in-flight prefetch fills) -> FMA -> store.

#define NB    4096
#define NCOEF 64
#define NCH   256
#define NT    68

__device__ float4 g_w4[NB];
__device__ int    g_base[NB];

__device__ __forceinline__ float gdiv(float a, float d) {
    return (d == 0.0f) ? 0.0f : __fdividef(a, d);
}

// ---------------------------------------------------------------- kernel 1
__global__ __launch_bounds__(256)
void span_kernel(const float* __restrict__ coef,   // [B, 64, 256]
                 const float* __restrict__ knots,  // [B, 68]
                 const float* __restrict__ inpce)  // [B, 1]
{
    const int lane = threadIdx.x & 31;
    const int b    = blockIdx.x * 8 + (threadIdx.x >> 5);

    const float* kt = knots + b * NT;
    const float  x  = __ldg(inpce + b);

    // span via count: one LDG.128 per lane covers all 68 knots
    float4 kv = __ldg((const float4*)kt + min(lane, 16));
    int cnt = 0;
    if (lane <= 16) {
        cnt = (kv.x <= x) + (kv.y <= x) + (kv.z <= x) + (kv.w <= x);
    }
    const int total = __reduce_add_sync(0xffffffffu, cnt);
    const int j     = total - 1;
    const bool valid = (total >= 1 && total <= NT - 1);
    const int jc = valid ? j : 3;
    const int base = valid ? min(max(jc - 3, 0), NCOEF - 4) : 0;

    // ---- prefetch this row's 4 KB coef window into L2 ASAP ----
    if (lane == 0) {
        const void* p = (const void*)(coef + (long long)b * (NCOEF * NCH) + base * NCH);
        asm volatile("cp.async.bulk.prefetch.L2.global [%0], %1;"
                     :: "l"(p), "r"(4096) : "memory");
    }

    // knot window t[jc-3 .. jc+4] (clamped loads; L1 hits)
    float tv[8];
    #pragma unroll
    for (int m = 0; m < 8; m++) {
        tv[m] = __ldg(kt + min(max(jc - 3 + m, 0), NT - 1));
    }

    float w0 = 0.f, w1 = 0.f, w2 = 0.f, w3 = 0.f;
    if (valid && j >= 3 && j <= NCOEF - 1) {
        // interior: t[j] <= x < t[j+1] => all denominators > 0, no guards
        float t0 = tv[1], t1 = tv[2], t2 = tv[3];
        float t3 = tv[4], t4 = tv[5], t5 = tv[6];

        float i1  = __fdividef(1.0f, t3 - t2);
        float b1m = (t3 - x) * i1;
        float b1c = (x - t2) * i1;

        float i20 = __fdividef(1.0f, t3 - t1);
        float i21 = __fdividef(1.0f, t4 - t2);
        float b2a = (t3 - x) * i20 * b1m;
        float b2b = (x - t1) * i20 * b1m + (t4 - x) * i21 * b1c;
        float b2c = (x - t2) * i21 * b1c;

        float i30 = __fdividef(1.0f, t3 - t0);
        float i31 = __fdividef(1.0f, t4 - t1);
        float i32 = __fdividef(1.0f, t5 - t2);
        w0 = (t3 - x) * i30 * b2a;
        w1 = (x - t0) * i30 * b2a + (t4 - x) * i31 * b2b;
        w2 = (x - t1) * i31 * b2b + (t5 - x) * i32 * b2c;
        w3 = (x - t2) * i32 * b2c;
    } else if (valid) {
        // edge spans: fully guarded reference recurrence on the tv window
        #define TV(i) tv[(i) - (j - 3)]
        float B1[4];
        #pragma unroll
        for (int q = 0; q < 4; q++) {
            int i = j - 2 + q;
            float v = 0.f;
            if (i >= 0 && i <= NT - 3) {
                if (i == j)     v += gdiv(x - TV(i),     TV(i + 1) - TV(i));
                if (i + 1 == j) v += gdiv(TV(i + 2) - x, TV(i + 2) - TV(i + 1));
            }
            B1[q] = v;
        }
        float B2[5];
        #pragma unroll
        for (int q = 0; q < 5; q++) {
            int i = j - 3 + q;
            float v = 0.f;
            if (i >= 0 && i <= NT - 4) {
                float a1 = gdiv(x - TV(i),     TV(i + 2) - TV(i));
                float a2 = gdiv(TV(i + 3) - x, TV(i + 3) - TV(i + 1));
                float u1 = (q >= 1) ? B1[q - 1] : 0.f;
                float u2 = (q <= 3) ? B1[q]     : 0.f;
                v = a1 * u1 + a2 * u2;
            }
            B2[q] = v;
        }
        #pragma unroll
        for (int q = 0; q < 4; q++) {
            int n = j - 3 + q;
            float v = 0.f;
            if (n >= 0 && n <= NT - 5) {
                float a1 = gdiv(x - TV(n),     TV(n + 3) - TV(n));
                float a2 = gdiv(TV(n + 4) - x, TV(n + 4) - TV(n + 1));
                v = a1 * B2[q] + a2 * B2[q + 1];
            }
            if (q == 0) w0 = v; else if (q == 1) w1 = v;
            else if (q == 2) w2 = v; else w3 = v;
        }
        #undef TV
    }

    // remap weights onto the consecutive window [base, base+3]
    float ww[4] = {0.f, 0.f, 0.f, 0.f};
    if (valid) {
        const float wq[4] = {w0, w1, w2, w3};
        #pragma unroll
        for (int q = 0; q < 4; q++) {
            int n = jc - 3 + q;            // true basis index for weight q
            int s = n - base;              // slot in the consecutive window
            if (n >= 0 && n < NCOEF && s >= 0 && s < 4) ww[s] += wq[q];
        }
    }

    if (lane == 0) {
        g_w4[b]   = make_float4(ww[0], ww[1], ww[2], ww[3]);
        g_base[b] = base;
    }
}

// ---------------------------------------------------------------- kernel 2
__global__ __launch_bounds__(128)
void gather_kernel(const float* __restrict__ coef,  // [B, 64, 256]
                   float* __restrict__ out)         // [B, 256]
{
    const int lane = threadIdx.x & 31;
    const int b    = blockIdx.x * 4 + (threadIdx.x >> 5);

    // both scratch loads are L2 hits (80 KB written by kernel 1)
    const float4 w  = g_w4[b];
    const int    nb = g_base[b];

    // 8x LDG.128 from the contiguous 4 KB window coef[b, nb..nb+3, :]
    const float4* cr = (const float4*)(coef + (long long)b * (NCOEF * NCH)) + nb * 64;
    float4 r00 = __ldg(cr + lane);
    float4 r01 = __ldg(cr + lane + 32);
    float4 r10 = __ldg(cr + 64 + lane);
    float4 r11 = __ldg(cr + 64 + lane + 32);
    float4 r20 = __ldg(cr + 128 + lane);
    float4 r21 = __ldg(cr + 128 + lane + 32);
    float4 r30 = __ldg(cr + 192 + lane);
    float4 r31 = __ldg(cr + 192 + lane + 32);

    float4 a0, a1;
    a0.x = w.x * r00.x + w.y * r10.x + w.z * r20.x + w.w * r30.x;
    a0.y = w.x * r00.y + w.y * r10.y + w.z * r20.y + w.w * r30.y;
    a0.z = w.x * r00.z + w.y * r10.z + w.z * r20.z + w.w * r30.z;
    a0.w = w.x * r00.w + w.y * r10.w + w.z * r20.w + w.w * r30.w;
    a1.x = w.x * r01.x + w.y * r11.x + w.z * r21.x + w.w * r31.x;
    a1.y = w.x * r01.y + w.y * r11.y + w.z * r21.y + w.w * r31.y;
    a1.z = w.x * r01.z + w.y * r11.z + w.z * r21.z + w.w * r31.z;
    a1.w = w.x * r01.w + w.y * r11.w + w.z * r21.w + w.w * r31.w;

    float4* o = (float4*)(out + (long long)b * NCH);
    o[lane]      = a0;
    o[lane + 32] = a1;
}

extern "C" void kernel_launch(void* const* d_in, const int* in_sizes, int n_in,
                              void* d_out, int out_size) {
    const float* coef  = (const float*)d_in[0];  // [4096, 64, 256]
    const float* knots = (const float*)d_in[1];  // [4096, 68]
    const float* inpce = (const float*)d_in[2];  // [4096, 1]
    float* out = (float*)d_out;                  // [4096, 256]

    span_kernel<<<NB / 8, 256>>>(coef, knots, inpce);
    gather_kernel<<<NB / 4, 128>>>(coef, out);
}

// round 12
// speedup vs baseline: 1.6232x; 1.6232x over previous
#include <cuda_runtime.h>
#include <cuda_bf16.h>
#include <cstdint>

// BSplineNN: out[b,c] = sum_n coef[b,n,c] * B_{n,3}(x_b)
// B=4096, n=64, C=256, K=3, T=68.  One WARP per batch row.
// The coefficient gather uses cp.async.bulk (TMA-engine bulk copy) into
// SMEM instead of LDG: the LDG demand-miss path caps at ~2.2 TB/s on this
// pattern (per-SM miss tracking), while the bulk/async path is serviced
// at the LTS cap. Per warp:
//   span via count (1x LDG.128 + REDUX) -> lane0 issues ONE 4 KB bulk copy
//   of coef[b, base..base+3, :] (1 KB-aligned) with mbarrier complete_tx
//   -> closed-form weights overlap the copy -> try_wait -> LDS.128 -> FMA.
// Weights remapped onto the consecutive window [base, base+3] (edge spans
// sum into clamped slots), matching the guarded reference recurrence.

#define NB    4096
#define NCOEF 64
#define NCH   256
#define NT    68
#define WARPS 4

__device__ __forceinline__ float gdiv(float a, float d) {
    return (d == 0.0f) ? 0.0f : __fdividef(a, d);
}

__global__ __launch_bounds__(WARPS * 32)
void bspline_kernel(const float* __restrict__ coef,   // [B, 64, 256]
                    const float* __restrict__ knots,  // [B, 68]
                    const float* __restrict__ inpce,  // [B, 1]
                    float* __restrict__ out)          // [B, 256]
{
    __shared__ __align__(128) float s_coef[WARPS][4 * NCH];   // 4 KB per warp
    __shared__ __align__(8)   unsigned long long s_mbar[WARPS];

    const int warp = threadIdx.x >> 5;
    const int lane = threadIdx.x & 31;
    const int b    = blockIdx.x * WARPS + warp;

    const uint32_t mbar = (uint32_t)__cvta_generic_to_shared(&s_mbar[warp]);

    // ---- mbarrier init (fresh each launch; phase parity starts at 0) ----
    if (lane == 0) {
        asm volatile("mbarrier.init.shared.b64 [%0], 1;" :: "r"(mbar) : "memory");
    }
    asm volatile("fence.proxy.async.shared::cta;" ::: "memory");
    __syncwarp();

    const float* kt = knots + b * NT;
    const float  x  = __ldg(inpce + b);

    // ---- span via count: one LDG.128 per lane covers all 68 knots ----
    float4 kv = __ldg((const float4*)kt + min(lane, 16));
    int cnt = 0;
    if (lane <= 16) {
        cnt = (kv.x <= x) + (kv.y <= x) + (kv.z <= x) + (kv.w <= x);
    }
    const int total = __reduce_add_sync(0xffffffffu, cnt);   // #knots <= x
    const int j     = total - 1;
    const bool valid = (total >= 1 && total <= NT - 1);      // t[j]<=x<t[j+1]
    const int jc   = valid ? j : 3;
    const int base = valid ? min(max(jc - 3, 0), NCOEF - 4) : 0;

    // ---- ONE bulk copy: coef[b, base..base+3, :] (4 KB, 1 KB-aligned) ----
    if (lane == 0) {
        asm volatile("mbarrier.arrive.expect_tx.shared.b64 _, [%0], %1;"
                     :: "r"(mbar), "r"(4096) : "memory");
        const void* src = (const void*)(coef + (long long)b * (NCOEF * NCH) + base * NCH);
        uint32_t dst = (uint32_t)__cvta_generic_to_shared(&s_coef[warp][0]);
        asm volatile("cp.async.bulk.shared::cta.global.mbarrier::complete_tx::bytes "
                     "[%0], [%1], %2, [%3];"
                     :: "r"(dst), "l"(src), "r"(4096), "r"(mbar) : "memory");
    }

    // ---- weights (overlap the bulk copy; knot reloads are L1 hits) ----
    float tv[8];
    #pragma unroll
    for (int m = 0; m < 8; m++) {
        tv[m] = __ldg(kt + min(max(jc - 3 + m, 0), NT - 1));
    }

    float w0 = 0.f, w1 = 0.f, w2 = 0.f, w3 = 0.f;
    if (valid && j >= 3 && j <= NCOEF - 1) {
        // interior: t[j] <= x < t[j+1] => all denominators > 0, no guards
        float t0 = tv[1], t1 = tv[2], t2 = tv[3];
        float t3 = tv[4], t4 = tv[5], t5 = tv[6];

        float i1  = __fdividef(1.0f, t3 - t2);
        float b1m = (t3 - x) * i1;
        float b1c = (x - t2) * i1;

        float i20 = __fdividef(1.0f, t3 - t1);
        float i21 = __fdividef(1.0f, t4 - t2);
        float b2a = (t3 - x) * i20 * b1m;
        float b2b = (x - t1) * i20 * b1m + (t4 - x) * i21 * b1c;
        float b2c = (x - t2) * i21 * b1c;

        float i30 = __fdividef(1.0f, t3 - t0);
        float i31 = __fdividef(1.0f, t4 - t1);
        float i32 = __fdividef(1.0f, t5 - t2);
        w0 = (t3 - x) * i30 * b2a;
        w1 = (x - t0) * i30 * b2a + (t4 - x) * i31 * b2b;
        w2 = (x - t1) * i31 * b2b + (t5 - x) * i32 * b2c;
        w3 = (x - t2) * i32 * b2c;
    } else if (valid) {
        // edge spans: fully guarded reference recurrence on the tv window
        #define TV(i) tv[(i) - (j - 3)]
        float B1[4];
        #pragma unroll
        for (int q = 0; q < 4; q++) {
            int i = j - 2 + q;
            float v = 0.f;
            if (i >= 0 && i <= NT - 3) {
                if (i == j)     v += gdiv(x - TV(i),     TV(i + 1) - TV(i));
                if (i + 1 == j) v += gdiv(TV(i + 2) - x, TV(i + 2) - TV(i + 1));
            }
            B1[q] = v;
        }
        float B2[5];
        #pragma unroll
        for (int q = 0; q < 5; q++) {
            int i = j - 3 + q;
            float v = 0.f;
            if (i >= 0 && i <= NT - 4) {
                float a1 = gdiv(x - TV(i),     TV(i + 2) - TV(i));
                float a2 = gdiv(TV(i + 3) - x, TV(i + 3) - TV(i + 1));
                float u1 = (q >= 1) ? B1[q - 1] : 0.f;
                float u2 = (q <= 3) ? B1[q]     : 0.f;
                v = a1 * u1 + a2 * u2;
            }
            B2[q] = v;
        }
        #pragma unroll
        for (int q = 0; q < 4; q++) {
            int n = j - 3 + q;
            float v = 0.f;
            if (n >= 0 && n <= NT - 5) {
                float a1 = gdiv(x - TV(n),     TV(n + 3) - TV(n));
                float a2 = gdiv(TV(n + 4) - x, TV(n + 4) - TV(n + 1));
                v = a1 * B2[q] + a2 * B2[q + 1];
            }
            if (q == 0) w0 = v; else if (q == 1) w1 = v;
            else if (q == 2) w2 = v; else w3 = v;
        }
        #undef TV
    }

    // remap weights onto the consecutive window [base, base+3]
    float ww0 = 0.f, ww1 = 0.f, ww2 = 0.f, ww3 = 0.f;
    if (valid) {
        const float wq[4] = {w0, w1, w2, w3};
        #pragma unroll
        for (int q = 0; q < 4; q++) {
            int n = jc - 3 + q;            // true basis index of weight q
            int s = n - base;              // slot in the consecutive window
            if (n >= 0 && n < NCOEF && s >= 0 && s < 4) {
                if (s == 0) ww0 += wq[q];
                else if (s == 1) ww1 += wq[q];
                else if (s == 2) ww2 += wq[q];
                else ww3 += wq[q];
            }
        }
    }

    // ---- wait for the bulk copy (parity 0) ----
    {
        uint32_t done;
        asm volatile(
            "{\n\t.reg .pred p;\n\t"
            "mbarrier.try_wait.parity.acquire.cta.shared::cta.b64 p, [%1], %2;\n\t"
            "selp.b32 %0, 1, 0, p;\n\t}"
            : "=r"(done) : "r"(mbar), "r"(0u) : "memory");
        while (!done) {
            asm volatile(
                "{\n\t.reg .pred p;\n\t"
                "mbarrier.try_wait.parity.acquire.cta.shared::cta.b64 p, [%1], %2, 0x989680;\n\t"
                "selp.b32 %0, 1, 0, p;\n\t}"
                : "=r"(done) : "r"(mbar), "r"(0u) : "memory");
        }
    }

    // ---- dot from SMEM (conflict-free LDS.128) + store ----
    const float4* sc = (const float4*)&s_coef[warp][0];   // 4 rows x 64 float4
    float4 r00 = sc[lane];
    float4 r01 = sc[lane + 32];
    float4 r10 = sc[64 + lane];
    float4 r11 = sc[64 + lane + 32];
    float4 r20 = sc[128 + lane];
    float4 r21 = sc[128 + lane + 32];
    float4 r30 = sc[192 + lane];
    float4 r31 = sc[192 + lane + 32];

    float4 a0, a1;
    a0.x = ww0 * r00.x + ww1 * r10.x + ww2 * r20.x + ww3 * r30.x;
    a0.y = ww0 * r00.y + ww1 * r10.y + ww2 * r20.y + ww3 * r30.y;
    a0.z = ww0 * r00.z + ww1 * r10.z + ww2 * r20.z + ww3 * r30.z;
    a0.w = ww0 * r00.w + ww1 * r10.w + ww2 * r20.w + ww3 * r30.w;
    a1.x = ww0 * r01.x + ww1 * r11.x + ww2 * r21.x + ww3 * r31.x;
    a1.y = ww0 * r01.y + ww1 * r11.y + ww2 * r21.y + ww3 * r31.y;
    a1.z = ww0 * r01.z + ww1 * r11.z + ww2 * r21.z + ww3 * r31.z;
    a1.w = ww0 * r01.w + ww1 * r11.w + ww2 * r21.w + ww3 * r31.w;

    float4* o = (float4*)(out + (long long)b * NCH);
    o[lane]      = a0;
    o[lane + 32] = a1;
}

extern "C" void kernel_launch(void* const* d_in, const int* in_sizes, int n_in,
                              void* d_out, int out_size) {
    const float* coef  = (const float*)d_in[0];  // [4096, 64, 256]
    const float* knots = (const float*)d_in[1];  // [4096, 68]
    const float* inpce = (const float*)d_in[2];  // [4096, 1]
    float* out = (float*)d_out;                  // [4096, 256]

    bspline_kernel<<<NB / WARPS, WARPS * 32>>>(coef, knots, inpce, out);
}